// round 9
// baseline (speedup 1.0000x reference)
#include <cuda_runtime.h>
#include <cuda_bf16.h>
#include <math.h>
#include <stdint.h>

// Problem constants
#define NN    4096
#define DD    64
#define HH    4
#define OO    64
#define KK    2
#define KHT   8        // K*H
#define NUSER 4000
#define CC    2
#define NW32  (NN / 32)            // mask words per row = 128
#define TOTAL_WORDS (KK * NN * NW32)   // 1,048,576

// Device scratch (allocation-free rule: static __device__ arrays)
__device__ __nv_bfloat16 g_hpT[KHT * OO * NN];   // h_prime transposed [kh][o][m] bf16 (4 MB)
__device__ float         g_att[KHT * NN * OO];   // attention output per (k,h)  (8 MB)
__device__ uint32_t      g_mask[TOTAL_WORDS];    // adjacency bitmask (4 MB)
__device__ float g_thr [KHT * NN];       // -src[n]
__device__ float g_es1 [KHT * NN];       // exp(src)
__device__ float g_es2 [KHT * NN];       // exp(0.2*src)
__device__ float g_dstv[KHT * NN];       // dst[m]
__device__ float g_ed1 [KHT * NN];       // exp(dst)
__device__ float g_ed2 [KHT * NN];       // exp(0.2*dst)

// ---------------------------------------------------------------------------
// Arch-agnostic tensor-core helpers (generic PTX, works on compute_103)
// ---------------------------------------------------------------------------
__device__ __forceinline__ uint32_t smem_u32(const void* p) {
    uint32_t a;
    asm("{ .reg .u64 t; cvta.to.shared.u64 t, %1; cvt.u32.u64 %0, t; }" : "=r"(a) : "l"(p));
    return a;
}
__device__ __forceinline__ void ldsm_x4(uint32_t* r, uint32_t addr) {
    asm volatile("ldmatrix.sync.aligned.m8n8.x4.shared.b16 {%0,%1,%2,%3}, [%4];"
        : "=r"(r[0]), "=r"(r[1]), "=r"(r[2]), "=r"(r[3]) : "r"(addr));
}
__device__ __forceinline__ void mma16816(float* c, const uint32_t* a, const uint32_t* b) {
    asm volatile("mma.sync.aligned.m16n8k16.row.col.f32.bf16.bf16.f32 "
        "{%0,%1,%2,%3}, {%4,%5,%6,%7}, {%8,%9}, {%0,%1,%2,%3};"
        : "+f"(c[0]), "+f"(c[1]), "+f"(c[2]), "+f"(c[3])
        : "r"(a[0]), "r"(a[1]), "r"(a[2]), "r"(a[3]), "r"(b[0]), "r"(b[1]));
}

// ---------------------------------------------------------------------------
// Kernel 0: pack adjacency (0/1 fp32, 128MB) into bitmask (4MB).
// Warp ballot: bit lane = column (m & 31); word index = m >> 5 global.
// ---------------------------------------------------------------------------
__global__ void k_pack(const float* __restrict__ adj) {
    const int lane = threadIdx.x & 31;
    const int nw   = (gridDim.x * blockDim.x) >> 5;
    int w = (blockIdx.x * blockDim.x + threadIdx.x) >> 5;
    for (; w < TOTAL_WORDS; w += nw) {
        const float v = adj[(size_t)w * 32 + lane];
        const uint32_t b = __ballot_sync(0xFFFFFFFFu, v != 0.0f);
        if (lane == 0) g_mask[w] = b;
    }
}

// ---------------------------------------------------------------------------
// Kernel 1 (fused): h_prime = h @ w  ->  bf16 transposed copy (MMA B operand)
//                   + tanh / a_src / a_dst dots + factorized exponentials.
// grid (N/64, KH), 256 threads.
// ---------------------------------------------------------------------------
__global__ void k_hproj(const float* __restrict__ h, const float* __restrict__ w,
                        const float* __restrict__ a_src, const float* __restrict__ a_dst) {
    const int kh = blockIdx.y;
    const int n0 = blockIdx.x * 64;
    __shared__ float shT[64][68];     // [d][i]  (transposed h tile)
    __shared__ float buf[64 * 68];    // first 4096 floats: w tile; reused as [o][n] (stride 68)
    __shared__ float sa[128];         // a_src[kh][o], a_dst[kh][o]
    const int tid = threadIdx.x;

    if (tid < 64) {
        sa[tid]      = a_src[kh * 64 + tid];
        sa[64 + tid] = a_dst[kh * 64 + tid];
    }

    const float4* wkh = (const float4*)(w + (size_t)kh * 64 * 64);
    #pragma unroll
    for (int it = 0; it < 4; it++) ((float4*)buf)[tid + it * 256] = wkh[tid + it * 256];

    {
        const int d = tid & 63, ig0 = tid >> 6;
        #pragma unroll
        for (int it = 0; it < 4; it++) {
            const int ig = ig0 + it * 4;
            float4 v;
            v.x = h[(size_t)(n0 + ig * 4 + 0) * DD + d];
            v.y = h[(size_t)(n0 + ig * 4 + 1) * DD + d];
            v.z = h[(size_t)(n0 + ig * 4 + 2) * DD + d];
            v.w = h[(size_t)(n0 + ig * 4 + 3) * DD + d];
            *(float4*)&shT[d][ig * 4] = v;
        }
    }
    __syncthreads();

    const int ty = tid >> 4, tx = tid & 15;
    float acc[4][4] = {};
    #pragma unroll 8
    for (int j = 0; j < 64; j++) {
        const float4 pv = *(const float4*)&shT[j][ty * 4];
        const float4 hv = *(const float4*)&buf[j * 64 + tx * 4];
        acc[0][0] += pv.x * hv.x; acc[0][1] += pv.x * hv.y; acc[0][2] += pv.x * hv.z; acc[0][3] += pv.x * hv.w;
        acc[1][0] += pv.y * hv.x; acc[1][1] += pv.y * hv.y; acc[1][2] += pv.y * hv.z; acc[1][3] += pv.y * hv.w;
        acc[2][0] += pv.z * hv.x; acc[2][1] += pv.z * hv.y; acc[2][2] += pv.z * hv.z; acc[2][3] += pv.z * hv.w;
        acc[3][0] += pv.w * hv.x; acc[3][1] += pv.w * hv.y; acc[3][2] += pv.w * hv.z; acc[3][3] += pv.w * hv.w;
    }

    // ---- fused attvec: per-row tanh-dot partials, reduce across tx ----
    {
        float pas[4] = {}, pad[4] = {};
        #pragma unroll
        for (int r = 0; r < 4; r++)
            #pragma unroll
            for (int c = 0; c < 4; c++) {
                const float t = tanhf(acc[r][c]);
                pas[r] += t * sa[tx * 4 + c];
                pad[r] += t * sa[64 + tx * 4 + c];
            }
        #pragma unroll
        for (int off = 1; off < 16; off <<= 1)
            #pragma unroll
            for (int r = 0; r < 4; r++) {
                pas[r] += __shfl_xor_sync(0xFFFFFFFFu, pas[r], off);
                pad[r] += __shfl_xor_sync(0xFFFFFFFFu, pad[r], off);
            }
        if (tx == 0) {
            #pragma unroll
            for (int r = 0; r < 4; r++) {
                const int idx = kh * NN + n0 + ty * 4 + r;
                const float as = pas[r], ad = pad[r];
                g_thr [idx] = -as;
                g_es1 [idx] = expf(as);
                g_es2 [idx] = expf(0.2f * as);
                g_dstv[idx] = ad;
                g_ed1 [idx] = expf(ad);
                g_ed2 [idx] = expf(0.2f * ad);
            }
        }
    }

    __syncthreads();            // done reading buf as w-tile
    // transpose into buf as [o][n_local], stride 68 to avoid conflicts
    #pragma unroll
    for (int r = 0; r < 4; r++)
        #pragma unroll
        for (int c = 0; c < 4; c++)
            buf[(tx * 4 + c) * 68 + ty * 4 + r] = acc[r][c];
    __syncthreads();
    // write bf16 transposed rows: thread -> row o = tid>>2, 16 n values
    {
        const int o = tid >> 2, nc = (tid & 3) * 16;
        __nv_bfloat162 tmp[8];
        #pragma unroll
        for (int j = 0; j < 8; j++)
            tmp[j] = __floats2bfloat162_rn(buf[o * 68 + nc + 2 * j], buf[o * 68 + nc + 2 * j + 1]);
        __nv_bfloat16* dst = g_hpT + ((size_t)kh * 64 + o) * NN + n0 + nc;
        *(uint4*)dst       = ((uint4*)tmp)[0];
        *(uint4*)(dst + 8) = ((uint4*)tmp)[1];
    }
}

// ---------------------------------------------------------------------------
// Kernel 2 (dominant, mma.sync bf16): ONE head per CTA, bitmask adjacency.
//   D[128,64] += P[128,64]_bf16 @ HpT[64(o),64(m)]_bf16^T   (chunks over m)
//   P[n,m] = bit(k,n,m) * (dst[m] >= -src[n] ? es1[n]*ed1[m] : es2[n]*ed2[m])
// grid (N/128=32, K=2, H=4), 256 threads (8 warps), dynamic smem ~30KB.
//
// smem (bytes from base):
//   P tile : [128 rows x 72 bf16 (144B stride)] = 18432
//   B tile : [ 64 rows x 72 bf16 (144B stride)] =  9216
//   row consts: 3 x 128 floats                  =  1536
//   den    : 128 floats                         =   512
// ---------------------------------------------------------------------------
#define P_OFF   0
#define B_OFF   18432
#define RC_OFF  27648
#define D_OFF   29184
#define SMEM_DYN 29696

__global__ void __launch_bounds__(256, 2) k_main6() {
    extern __shared__ char sm[];
    const uint32_t smb = smem_u32(sm);
    const int tid  = threadIdx.x;
    const int wid  = tid >> 5;
    const int lane = tid & 31;
    const int k    = blockIdx.y;
    const int hh   = blockIdx.z;
    const int n0   = blockIdx.x * 128;
    const int kh   = k * HH + hh;

    // stage row-side constants into smem (visible after first loop sync)
    if (tid < 128) {
        const int ridx = kh * NN + n0 + tid;
        ((float*)(sm + RC_OFF))[tid]       = g_thr[ridx];
        ((float*)(sm + RC_OFF))[128 + tid] = g_es1[ridx];
        ((float*)(sm + RC_OFF))[256 + tid] = g_es2[ridx];
    }

    // P-build mapping: fixed cols, walk rows
    const int g     = tid >> 4;          // 0..15
    const int cbase = (tid & 15) * 4;    // 0..60
    const int wsel  = cbase >> 5;        // word within row pair
    const int shift = cbase & 31;
    const uint32_t* mrow = g_mask + (size_t)k * NN * NW32 + (size_t)(n0 + g) * NW32 + wsel;
    const float* mdv = g_dstv + kh * NN;
    const float* me1 = g_ed1  + kh * NN;
    const float* me2 = g_ed2  + kh * NN;

    // B tile load mapping: 64 rows x 64 bf16 = 512 uint4, 2 per thread
    const int brow0 = tid >> 3,          bcol0 = tid & 7;
    const int brow1 = (tid + 256) >> 3,  bcol1 = tid & 7;

    // mma warp mapping: warp -> (row slab = wid&3, o-half = wid>>2)
    const int slab  = wid & 3;
    const int ohalf = wid >> 2;
    const int mbase = slab * 32;
    const int a_row = ((lane >> 3) & 1) * 8 + (lane & 7);
    const int a_k   = (lane >> 4) * 8;
    const uint32_t aAddr = smb + P_OFF + (mbase + a_row) * 144 + a_k * 2;
    const int b_n = ((lane >> 4) & 1) * 8 + (lane & 7);
    const int b_k = ((lane >> 3) & 1) * 8;
    const uint32_t bAddr = smb + B_OFF + (ohalf * 32 + b_n) * 144 + b_k * 2;

    float acc[2][4][4];     // [row 16-slab][o-frag][c]
    #pragma unroll
    for (int a = 0; a < 2; a++)
        #pragma unroll
        for (int b = 0; b < 4; b++)
            #pragma unroll
            for (int cc = 0; cc < 4; cc++) acc[a][b][cc] = 0.0f;
    float den[8];
    #pragma unroll
    for (int j = 0; j < 8; j++) den[j] = 0.0f;

    const float* sthr = (const float*)(sm + RC_OFF);

    for (int c = 0; c < NN / 64; c++) {
        const int mt = c << 6;
        // ---- prefetch gmem to registers ----
        uint32_t mw[8];
        #pragma unroll
        for (int j = 0; j < 8; j++)
            mw[j] = mrow[(size_t)(j * 16) * NW32 + (mt >> 5)];
        const uint4 bq0 = *(const uint4*)(g_hpT + ((size_t)kh * 64 + brow0) * NN + mt + bcol0 * 8);
        const uint4 bq1 = *(const uint4*)(g_hpT + ((size_t)kh * 64 + brow1) * NN + mt + bcol1 * 8);
        const float4 dv4 = *(const float4*)(mdv + mt + cbase);
        const float4 q14 = *(const float4*)(me1 + mt + cbase);
        const float4 q24 = *(const float4*)(me2 + mt + cbase);

        __syncthreads();   // prior chunk's ldsm reads complete (also orders RC stage on c==0)

        // ---- stage B ----
        *(uint4*)(sm + B_OFF + brow0 * 144 + bcol0 * 16) = bq0;
        *(uint4*)(sm + B_OFF + brow1 * 144 + bcol1 * 16) = bq1;

        // ---- build P tile (bf16): 8 rows x 4 cols per thread ----
        #pragma unroll
        for (int j = 0; j < 8; j++) {
            const int row = g + j * 16;
            const float thr = sthr[row];
            const float e1  = sthr[128 + row];
            const float e2  = sthr[256 + row];
            const uint32_t bits = mw[j] >> shift;
            const float v0 = (dv4.x >= thr) ? e1 * q14.x : e2 * q24.x;
            const float v1 = (dv4.y >= thr) ? e1 * q14.y : e2 * q24.y;
            const float v2 = (dv4.z >= thr) ? e1 * q14.z : e2 * q24.z;
            const float v3 = (dv4.w >= thr) ? e1 * q14.w : e2 * q24.w;
            const float p0 = (bits & 1u) ? v0 : 0.0f;
            const float p1 = (bits & 2u) ? v1 : 0.0f;
            const float p2 = (bits & 4u) ? v2 : 0.0f;
            const float p3 = (bits & 8u) ? v3 : 0.0f;
            den[j] += (p0 + p1) + (p2 + p3);
            __nv_bfloat162 lo = __floats2bfloat162_rn(p0, p1);
            __nv_bfloat162 hi = __floats2bfloat162_rn(p2, p3);
            uint2 v;
            v.x = *(uint32_t*)&lo;
            v.y = *(uint32_t*)&hi;
            *(uint2*)(sm + P_OFF + row * 144 + cbase * 2) = v;
        }
        __syncthreads();   // P + B tiles visible

        // ---- tensor cores: 32 x m16n8k16 per warp ----
        #pragma unroll
        for (int ks = 0; ks < 4; ks++) {
            uint32_t af0[4], af1[4];
            ldsm_x4(af0, aAddr + ks * 32);
            ldsm_x4(af1, aAddr + 16 * 144 + ks * 32);
            #pragma unroll
            for (int nt = 0; nt < 2; nt++) {
                uint32_t bf[4];
                ldsm_x4(bf, bAddr + nt * (16 * 144) + ks * 32);
                mma16816(acc[0][2 * nt],     af0, bf);
                mma16816(acc[0][2 * nt + 1], af0, bf + 2);
                mma16816(acc[1][2 * nt],     af1, bf);
                mma16816(acc[1][2 * nt + 1], af1, bf + 2);
            }
        }
    }

    // ---- denominator reduce: 16 col-owner lanes per row ----
    #pragma unroll
    for (int j = 0; j < 8; j++) {
        float v = den[j];
        v += __shfl_xor_sync(0xFFFFFFFFu, v, 8);
        v += __shfl_xor_sync(0xFFFFFFFFu, v, 4);
        v += __shfl_xor_sync(0xFFFFFFFFu, v, 2);
        v += __shfl_xor_sync(0xFFFFFFFFu, v, 1);
        if ((tid & 15) == 0)
            ((float*)(sm + D_OFF))[g + j * 16] = v;
    }
    __syncthreads();

    // ---- epilogue: scale by 1/den, store ----
    const float* sden = (const float*)(sm + D_OFF);
    #pragma unroll
    for (int mt2 = 0; mt2 < 2; mt2++) {
        const int row0 = mbase + mt2 * 16 + (lane >> 2);
        const float inv0 = 1.0f / sden[row0];
        const float inv1 = 1.0f / sden[row0 + 8];
        float* op0 = g_att + ((size_t)kh * NN + n0 + row0) * OO;
        float* op1 = op0 + 8 * OO;
        #pragma unroll
        for (int j = 0; j < 4; j++) {
            const int col = ohalf * 32 + j * 8 + (lane & 3) * 2;
            float2 v0 = make_float2(acc[mt2][j][0] * inv0, acc[mt2][j][1] * inv0);
            float2 v1 = make_float2(acc[mt2][j][2] * inv1, acc[mt2][j][3] * inv1);
            *(float2*)(op0 + col) = v0;
            *(float2*)(op1 + col) = v1;
        }
    }
}

// ---------------------------------------------------------------------------
// Kernel 3: head-mean -> concat -> fc (C=2) -> log_softmax.
// ---------------------------------------------------------------------------
__global__ void k_final(const float* __restrict__ fc_w, const float* __restrict__ fc_b,
                        float* __restrict__ out) {
    const int wg = blockIdx.x * 8 + (threadIdx.x >> 5);
    if (wg >= NUSER) return;
    const int lane = threadIdx.x & 31;
    const int n = wg;

    float l0 = 0.0f, l1 = 0.0f;
    #pragma unroll
    for (int u = 0; u < 4; u++) {
        const int d = lane + u * 32;
        const int k = d >> 6, o = d & 63;
        float e = 0.0f;
        #pragma unroll
        for (int h = 0; h < HH; h++)
            e += g_att[(((size_t)(k * HH + h) * NN) + n) * OO + o];
        e *= 0.25f;
        l0 += e * fc_w[d];
        l1 += e * fc_w[128 + d];
    }
    #pragma unroll
    for (int off = 16; off; off >>= 1) {
        l0 += __shfl_xor_sync(0xFFFFFFFFu, l0, off);
        l1 += __shfl_xor_sync(0xFFFFFFFFu, l1, off);
    }
    if (lane == 0) {
        l0 += fc_b[0];
        l1 += fc_b[1];
        const float mx  = fmaxf(l0, l1);
        const float lse = mx + logf(expf(l0 - mx) + expf(l1 - mx));
        out[n * 2 + 0] = l0 - lse;
        out[n * 2 + 1] = l1 - lse;
    }
}

// ---------------------------------------------------------------------------
extern "C" void kernel_launch(void* const* d_in, const int* in_sizes, int n_in,
                              void* d_out, int out_size) {
    (void)in_sizes; (void)n_in; (void)out_size;
    const float* h     = (const float*)d_in[0];
    const float* hadj  = (const float*)d_in[1];
    const float* w     = (const float*)d_in[2];
    const float* a_src = (const float*)d_in[3];
    const float* a_dst = (const float*)d_in[4];
    const float* fc_w  = (const float*)d_in[5];
    const float* fc_b  = (const float*)d_in[6];
    float* out = (float*)d_out;

    static int smem_set = 0;
    if (!smem_set) {
        cudaFuncSetAttribute(k_main6, cudaFuncAttributeMaxDynamicSharedMemorySize, SMEM_DYN);
        smem_set = 1;
    }

    k_pack  <<<2048, 256>>>(hadj);
    k_hproj <<<dim3(NN / 64, KHT), 256>>>(h, w, a_src, a_dst);
    k_main6 <<<dim3(NN / 128, KK, HH), 256, SMEM_DYN>>>();
    k_final <<<NUSER / 8, 256>>>(fc_w, fc_b, out);
}

// round 10
// speedup vs baseline: 1.2057x; 1.2057x over previous
#include <cuda_runtime.h>
#include <cuda_bf16.h>
#include <math.h>
#include <stdint.h>

// Problem constants
#define NN    4096
#define DD    64
#define HH    4
#define OO    64
#define KK    2
#define KHT   8        // K*H
#define NUSER 4000
#define CC    2

// Device scratch (allocation-free rule: static __device__ arrays)
__device__ __nv_bfloat16 g_hpT[KHT * OO * NN];   // h_prime transposed [kh][o][m] bf16 (4 MB)
__device__ float         g_att[KHT * NN * OO];   // attention output per (k,h)  (8 MB)
__device__ float g_thr [KHT * NN];       // -src[n]
__device__ float g_es1 [KHT * NN];       // exp(src)
__device__ float g_es2 [KHT * NN];       // exp(0.2*src)
__device__ float g_dstv[KHT * NN];       // dst[m]
__device__ float g_ed1 [KHT * NN];       // exp(dst)
__device__ float g_ed2 [KHT * NN];       // exp(0.2*dst)

// ---------------------------------------------------------------------------
// Arch-agnostic tensor-core helpers (generic PTX, works on compute_103)
// ---------------------------------------------------------------------------
__device__ __forceinline__ uint32_t smem_u32(const void* p) {
    uint32_t a;
    asm("{ .reg .u64 t; cvta.to.shared.u64 t, %1; cvt.u32.u64 %0, t; }" : "=r"(a) : "l"(p));
    return a;
}
__device__ __forceinline__ void ldsm_x4(uint32_t* r, uint32_t addr) {
    asm volatile("ldmatrix.sync.aligned.m8n8.x4.shared.b16 {%0,%1,%2,%3}, [%4];"
        : "=r"(r[0]), "=r"(r[1]), "=r"(r[2]), "=r"(r[3]) : "r"(addr));
}
__device__ __forceinline__ void mma16816(float* c, const uint32_t* a, const uint32_t* b) {
    asm volatile("mma.sync.aligned.m16n8k16.row.col.f32.bf16.bf16.f32 "
        "{%0,%1,%2,%3}, {%4,%5,%6,%7}, {%8,%9}, {%0,%1,%2,%3};"
        : "+f"(c[0]), "+f"(c[1]), "+f"(c[2]), "+f"(c[3])
        : "r"(a[0]), "r"(a[1]), "r"(a[2]), "r"(a[3]), "r"(b[0]), "r"(b[1]));
}

// ---------------------------------------------------------------------------
// Kernel 1 (fused): h_prime = h @ w  ->  bf16 transposed copy (MMA B operand)
//                   + tanh / a_src / a_dst dots + factorized exponentials.
// grid (N/64, KH), 256 threads.
// ---------------------------------------------------------------------------
__global__ void k_hproj(const float* __restrict__ h, const float* __restrict__ w,
                        const float* __restrict__ a_src, const float* __restrict__ a_dst) {
    const int kh = blockIdx.y;
    const int n0 = blockIdx.x * 64;
    __shared__ float shT[64][68];     // [d][i]  (transposed h tile)
    __shared__ float buf[64 * 68];    // first 4096 floats: w tile; reused as [o][n] (stride 68)
    __shared__ float sa[128];         // a_src[kh][o], a_dst[kh][o]
    const int tid = threadIdx.x;

    if (tid < 64) {
        sa[tid]      = a_src[kh * 64 + tid];
        sa[64 + tid] = a_dst[kh * 64 + tid];
    }

    const float4* wkh = (const float4*)(w + (size_t)kh * 64 * 64);
    #pragma unroll
    for (int it = 0; it < 4; it++) ((float4*)buf)[tid + it * 256] = wkh[tid + it * 256];

    {
        const int d = tid & 63, ig0 = tid >> 6;
        #pragma unroll
        for (int it = 0; it < 4; it++) {
            const int ig = ig0 + it * 4;
            float4 v;
            v.x = h[(size_t)(n0 + ig * 4 + 0) * DD + d];
            v.y = h[(size_t)(n0 + ig * 4 + 1) * DD + d];
            v.z = h[(size_t)(n0 + ig * 4 + 2) * DD + d];
            v.w = h[(size_t)(n0 + ig * 4 + 3) * DD + d];
            *(float4*)&shT[d][ig * 4] = v;
        }
    }
    __syncthreads();

    const int ty = tid >> 4, tx = tid & 15;
    float acc[4][4] = {};
    #pragma unroll 8
    for (int j = 0; j < 64; j++) {
        const float4 pv = *(const float4*)&shT[j][ty * 4];
        const float4 hv = *(const float4*)&buf[j * 64 + tx * 4];
        acc[0][0] += pv.x * hv.x; acc[0][1] += pv.x * hv.y; acc[0][2] += pv.x * hv.z; acc[0][3] += pv.x * hv.w;
        acc[1][0] += pv.y * hv.x; acc[1][1] += pv.y * hv.y; acc[1][2] += pv.y * hv.z; acc[1][3] += pv.y * hv.w;
        acc[2][0] += pv.z * hv.x; acc[2][1] += pv.z * hv.y; acc[2][2] += pv.z * hv.z; acc[2][3] += pv.z * hv.w;
        acc[3][0] += pv.w * hv.x; acc[3][1] += pv.w * hv.y; acc[3][2] += pv.w * hv.z; acc[3][3] += pv.w * hv.w;
    }

    // ---- fused attvec: per-row tanh-dot partials, reduce across tx ----
    {
        float pas[4] = {}, pad[4] = {};
        #pragma unroll
        for (int r = 0; r < 4; r++)
            #pragma unroll
            for (int c = 0; c < 4; c++) {
                const float t = tanhf(acc[r][c]);
                pas[r] += t * sa[tx * 4 + c];
                pad[r] += t * sa[64 + tx * 4 + c];
            }
        #pragma unroll
        for (int off = 1; off < 16; off <<= 1)
            #pragma unroll
            for (int r = 0; r < 4; r++) {
                pas[r] += __shfl_xor_sync(0xFFFFFFFFu, pas[r], off);
                pad[r] += __shfl_xor_sync(0xFFFFFFFFu, pad[r], off);
            }
        if (tx == 0) {
            #pragma unroll
            for (int r = 0; r < 4; r++) {
                const int idx = kh * NN + n0 + ty * 4 + r;
                const float as = pas[r], ad = pad[r];
                g_thr [idx] = -as;
                g_es1 [idx] = expf(as);
                g_es2 [idx] = expf(0.2f * as);
                g_dstv[idx] = ad;
                g_ed1 [idx] = expf(ad);
                g_ed2 [idx] = expf(0.2f * ad);
            }
        }
    }

    __syncthreads();            // done reading buf as w-tile
    // transpose into buf as [o][n_local], stride 68 to avoid conflicts
    #pragma unroll
    for (int r = 0; r < 4; r++)
        #pragma unroll
        for (int c = 0; c < 4; c++)
            buf[(tx * 4 + c) * 68 + ty * 4 + r] = acc[r][c];
    __syncthreads();
    // write bf16 transposed rows: thread -> row o = tid>>2, 16 n values
    {
        const int o = tid >> 2, nc = (tid & 3) * 16;
        __nv_bfloat162 tmp[8];
        #pragma unroll
        for (int j = 0; j < 8; j++)
            tmp[j] = __floats2bfloat162_rn(buf[o * 68 + nc + 2 * j], buf[o * 68 + nc + 2 * j + 1]);
        __nv_bfloat16* dst = g_hpT + ((size_t)kh * 64 + o) * NN + n0 + nc;
        *(uint4*)dst       = ((uint4*)tmp)[0];
        *(uint4*)(dst + 8) = ((uint4*)tmp)[1];
    }
}

// ---------------------------------------------------------------------------
// Kernel 2 (dominant, mma.sync bf16): ONE head per CTA, coalesced adj loads,
// DOUBLE-BUFFERED P/B smem (1 sync per chunk) + software-pipelined prefetch.
//   D[128,64] += P[128,64]_bf16 @ HpT[64(o),64(m)]_bf16^T   (chunks over m)
//   P[n,m] = adj[k][n][m] * (dst[m] >= -src[n] ? es1[n]*ed1[m] : es2[n]*ed2[m])
// grid (N/128=32, K=2, H=4), 256 threads (8 warps), dynamic smem 56KB.
//
// smem (bytes from base):
//   P tiles: 2 x [128 rows x 72 bf16 (144B stride)] = 36864
//   B tiles: 2 x [ 64 rows x 72 bf16 (144B stride)] = 18432
//   row consts: 3 x 128 floats                      =  1536
//   den    : 128 floats                             =   512
// ---------------------------------------------------------------------------
#define P_OFF   0
#define PH_B    18432
#define B_OFF   36864
#define BH_B    9216
#define RC_OFF  55296
#define D_OFF   56832
#define SMEM_DYN 57344

__global__ void __launch_bounds__(256, 2) k_main7(const float* __restrict__ adj) {
    extern __shared__ char sm[];
    const uint32_t smb = smem_u32(sm);
    const int tid  = threadIdx.x;
    const int wid  = tid >> 5;
    const int lane = tid & 31;
    const int k    = blockIdx.y;
    const int hh   = blockIdx.z;
    const int n0   = blockIdx.x * 128;
    const int kh   = k * HH + hh;

    // stage row-side constants into smem
    if (tid < 128) {
        const int ridx = kh * NN + n0 + tid;
        ((float*)(sm + RC_OFF))[tid]       = g_thr[ridx];
        ((float*)(sm + RC_OFF))[128 + tid] = g_es1[ridx];
        ((float*)(sm + RC_OFF))[256 + tid] = g_es2[ridx];
    }

    // P-build mapping: fixed cols, walk rows
    const int g     = tid >> 4;          // 0..15
    const int cbase = (tid & 15) * 4;    // 0..60
    const float* adjbase = adj + (size_t)k * NN * NN + (size_t)n0 * NN;
    const float* mdv = g_dstv + kh * NN;
    const float* me1 = g_ed1  + kh * NN;
    const float* me2 = g_ed2  + kh * NN;

    // B tile load mapping: 64 rows x 64 bf16 = 512 uint4, 2 per thread
    const int brow0 = tid >> 3,          bcol0 = tid & 7;
    const int brow1 = (tid + 256) >> 3,  bcol1 = tid & 7;
    const __nv_bfloat16* hptk = g_hpT + (size_t)kh * 64 * NN;

    // mma warp mapping: warp -> (row slab = wid&3, o-half = wid>>2)
    const int slab  = wid & 3;
    const int ohalf = wid >> 2;
    const int mbase = slab * 32;
    const int a_row = ((lane >> 3) & 1) * 8 + (lane & 7);
    const int a_k   = (lane >> 4) * 8;
    const uint32_t aAddr = smb + P_OFF + (mbase + a_row) * 144 + a_k * 2;
    const int b_n = ((lane >> 4) & 1) * 8 + (lane & 7);
    const int b_k = ((lane >> 3) & 1) * 8;
    const uint32_t bAddr = smb + B_OFF + (ohalf * 32 + b_n) * 144 + b_k * 2;

    float acc[2][4][4];     // [row 16-slab][o-frag][c]
    #pragma unroll
    for (int a = 0; a < 2; a++)
        #pragma unroll
        for (int b = 0; b < 4; b++)
            #pragma unroll
            for (int cc = 0; cc < 4; cc++) acc[a][b][cc] = 0.0f;
    float den[8];
    #pragma unroll
    for (int j = 0; j < 8; j++) den[j] = 0.0f;

    const float* sthr = (const float*)(sm + RC_OFF);

    // ---- prefetch chunk 0 ----
    float4 a4[8];
    uint4  bq0, bq1;
    float4 dv4, q14, q24;
    {
        #pragma unroll
        for (int j = 0; j < 8; j++)
            a4[j] = *(const float4*)(adjbase + (size_t)(g + j * 16) * NN + cbase);
        bq0 = *(const uint4*)(hptk + (size_t)brow0 * NN + bcol0 * 8);
        bq1 = *(const uint4*)(hptk + (size_t)brow1 * NN + bcol1 * 8);
        dv4 = *(const float4*)(mdv + cbase);
        q14 = *(const float4*)(me1 + cbase);
        q24 = *(const float4*)(me2 + cbase);
    }
    __syncthreads();   // row consts visible

    for (int c = 0; c < NN / 64; c++) {
        const int buf = c & 1;

        // ---- stage B (from prefetched regs) ----
        *(uint4*)(sm + B_OFF + buf * BH_B + brow0 * 144 + bcol0 * 16) = bq0;
        *(uint4*)(sm + B_OFF + buf * BH_B + brow1 * 144 + bcol1 * 16) = bq1;

        // ---- build P tile (bf16): 8 rows x 4 cols per thread ----
        #pragma unroll
        for (int j = 0; j < 8; j++) {
            const int row = g + j * 16;
            const float thr = sthr[row];
            const float e1  = sthr[128 + row];
            const float e2  = sthr[256 + row];
            const float p0 = a4[j].x * ((dv4.x >= thr) ? e1 * q14.x : e2 * q24.x);
            const float p1 = a4[j].y * ((dv4.y >= thr) ? e1 * q14.y : e2 * q24.y);
            const float p2 = a4[j].z * ((dv4.z >= thr) ? e1 * q14.z : e2 * q24.z);
            const float p3 = a4[j].w * ((dv4.w >= thr) ? e1 * q14.w : e2 * q24.w);
            den[j] += (p0 + p1) + (p2 + p3);
            __nv_bfloat162 lo = __floats2bfloat162_rn(p0, p1);
            __nv_bfloat162 hi = __floats2bfloat162_rn(p2, p3);
            uint2 v;
            v.x = *(uint32_t*)&lo;
            v.y = *(uint32_t*)&hi;
            *(uint2*)(sm + P_OFF + buf * PH_B + row * 144 + cbase * 2) = v;
        }
        __syncthreads();   // this chunk's P + B visible; prior chunk's mma reads done

        // ---- prefetch chunk c+1 (LDG latency hidden under mma phase) ----
        if (c < NN / 64 - 1) {
            const int mt = (c + 1) << 6;
            #pragma unroll
            for (int j = 0; j < 8; j++)
                a4[j] = *(const float4*)(adjbase + (size_t)(g + j * 16) * NN + mt + cbase);
            bq0 = *(const uint4*)(hptk + (size_t)brow0 * NN + mt + bcol0 * 8);
            bq1 = *(const uint4*)(hptk + (size_t)brow1 * NN + mt + bcol1 * 8);
            dv4 = *(const float4*)(mdv + mt + cbase);
            q14 = *(const float4*)(me1 + mt + cbase);
            q24 = *(const float4*)(me2 + mt + cbase);
        }

        // ---- tensor cores: 32 x m16n8k16 per warp ----
        const uint32_t aB = aAddr + buf * PH_B;
        const uint32_t bB = bAddr + buf * BH_B;
        #pragma unroll
        for (int ks = 0; ks < 4; ks++) {
            uint32_t af0[4], af1[4];
            ldsm_x4(af0, aB + ks * 32);
            ldsm_x4(af1, aB + 16 * 144 + ks * 32);
            #pragma unroll
            for (int nt = 0; nt < 2; nt++) {
                uint32_t bf[4];
                ldsm_x4(bf, bB + nt * (16 * 144) + ks * 32);
                mma16816(acc[0][2 * nt],     af0, bf);
                mma16816(acc[0][2 * nt + 1], af0, bf + 2);
                mma16816(acc[1][2 * nt],     af1, bf);
                mma16816(acc[1][2 * nt + 1], af1, bf + 2);
            }
        }
    }

    // ---- denominator reduce: 16 col-owner lanes per row ----
    #pragma unroll
    for (int j = 0; j < 8; j++) {
        float v = den[j];
        v += __shfl_xor_sync(0xFFFFFFFFu, v, 8);
        v += __shfl_xor_sync(0xFFFFFFFFu, v, 4);
        v += __shfl_xor_sync(0xFFFFFFFFu, v, 2);
        v += __shfl_xor_sync(0xFFFFFFFFu, v, 1);
        if ((tid & 15) == 0)
            ((float*)(sm + D_OFF))[g + j * 16] = v;
    }
    __syncthreads();

    // ---- epilogue: scale by 1/den, store ----
    const float* sden = (const float*)(sm + D_OFF);
    #pragma unroll
    for (int mt2 = 0; mt2 < 2; mt2++) {
        const int row0 = mbase + mt2 * 16 + (lane >> 2);
        const float inv0 = 1.0f / sden[row0];
        const float inv1 = 1.0f / sden[row0 + 8];
        float* op0 = g_att + ((size_t)kh * NN + n0 + row0) * OO;
        float* op1 = op0 + 8 * OO;
        #pragma unroll
        for (int j = 0; j < 4; j++) {
            const int col = ohalf * 32 + j * 8 + (lane & 3) * 2;
            float2 v0 = make_float2(acc[mt2][j][0] * inv0, acc[mt2][j][1] * inv0);
            float2 v1 = make_float2(acc[mt2][j][2] * inv1, acc[mt2][j][3] * inv1);
            *(float2*)(op0 + col) = v0;
            *(float2*)(op1 + col) = v1;
        }
    }
}

// ---------------------------------------------------------------------------
// Kernel 3: head-mean -> concat -> fc (C=2) -> log_softmax.
// ---------------------------------------------------------------------------
__global__ void k_final(const float* __restrict__ fc_w, const float* __restrict__ fc_b,
                        float* __restrict__ out) {
    const int wg = blockIdx.x * 8 + (threadIdx.x >> 5);
    if (wg >= NUSER) return;
    const int lane = threadIdx.x & 31;
    const int n = wg;

    float l0 = 0.0f, l1 = 0.0f;
    #pragma unroll
    for (int u = 0; u < 4; u++) {
        const int d = lane + u * 32;
        const int k = d >> 6, o = d & 63;
        float e = 0.0f;
        #pragma unroll
        for (int h = 0; h < HH; h++)
            e += g_att[(((size_t)(k * HH + h) * NN) + n) * OO + o];
        e *= 0.25f;
        l0 += e * fc_w[d];
        l1 += e * fc_w[128 + d];
    }
    #pragma unroll
    for (int off = 16; off; off >>= 1) {
        l0 += __shfl_xor_sync(0xFFFFFFFFu, l0, off);
        l1 += __shfl_xor_sync(0xFFFFFFFFu, l1, off);
    }
    if (lane == 0) {
        l0 += fc_b[0];
        l1 += fc_b[1];
        const float mx  = fmaxf(l0, l1);
        const float lse = mx + logf(expf(l0 - mx) + expf(l1 - mx));
        out[n * 2 + 0] = l0 - lse;
        out[n * 2 + 1] = l1 - lse;
    }
}

// ---------------------------------------------------------------------------
extern "C" void kernel_launch(void* const* d_in, const int* in_sizes, int n_in,
                              void* d_out, int out_size) {
    (void)in_sizes; (void)n_in; (void)out_size;
    const float* h     = (const float*)d_in[0];
    const float* hadj  = (const float*)d_in[1];
    const float* w     = (const float*)d_in[2];
    const float* a_src = (const float*)d_in[3];
    const float* a_dst = (const float*)d_in[4];
    const float* fc_w  = (const float*)d_in[5];
    const float* fc_b  = (const float*)d_in[6];
    float* out = (float*)d_out;

    static int smem_set = 0;
    if (!smem_set) {
        cudaFuncSetAttribute(k_main7, cudaFuncAttributeMaxDynamicSharedMemorySize, SMEM_DYN);
        smem_set = 1;
    }

    k_hproj <<<dim3(NN / 64, KHT), 256>>>(h, w, a_src, a_dst);
    k_main7 <<<dim3(NN / 128, KK, HH), 256, SMEM_DYN>>>(hadj);
    k_final <<<NUSER / 8, 256>>>(fc_w, fc_b, out);
}